// round 2
// baseline (speedup 1.0000x reference)
#include <cuda_runtime.h>
#include <cuda_bf16.h>
#include <math.h>

#define NU 50000
#define NI 50000
#define HD 128
#define NE 800000
#define NG 512
#define NC 16
#define NL 3
#define BN_EPS 1e-5f

#define CDIV(a,b) (((a)+(b)-1)/(b))

// ---------------- scratch (static device globals; no runtime alloc) -------------
__device__ float g_xu[(size_t)NU*HD];
__device__ float g_xi[(size_t)NI*HD];
__device__ float g_aggu[(size_t)NU*HD];
__device__ float g_aggi[(size_t)NI*HD];
__device__ float g_newu[(size_t)NU*HD];
__device__ float g_newi[(size_t)NI*HD];
__device__ int   g_rowi[NI+1];
__device__ int   g_rowu[NU+1];
__device__ int   g_col_u2i[NE];
__device__ int   g_col_i2u[NE];
__device__ int   g_deg[NU];
__device__ int   g_cur[NU];
__device__ float g_stats[NL*2*2*HD];   // [layer][type(0=user,1=item)][sum|sumsq][ch]
__device__ float g_WcTu[256*HD];
__device__ float g_WcTi[256*HD];
__device__ int   g_su[NG+1];
__device__ int   g_si[NG+1];

// ---------------- small utility kernels ----------------------------------------
__global__ void k_copy4(float* __restrict__ dst, const float* __restrict__ src, int n4) {
    int i = blockIdx.x * blockDim.x + threadIdx.x;
    if (i < n4) ((float4*)dst)[i] = ((const float4*)src)[i];
}
__global__ void k_zero_f(float* p, int n) {
    int i = blockIdx.x * blockDim.x + threadIdx.x;
    if (i < n) p[i] = 0.f;
}
__global__ void k_zero_i(int* p, int n) {
    int i = blockIdx.x * blockDim.x + threadIdx.x;
    if (i < n) p[i] = 0;
}

// group offsets via lower_bound on sorted batch ids
__global__ void k_offsets(const int* __restrict__ batch, int n, int* __restrict__ off) {
    int g = blockIdx.x * blockDim.x + threadIdx.x;
    if (g > NG) return;
    int lo = 0, hi = n;
    while (lo < hi) { int mid = (lo + hi) >> 1; if (batch[mid] < g) lo = mid + 1; else hi = mid; }
    off[g] = lo;
}

// ---------------- CSR build -----------------------------------------------------
__global__ void k_hist(const int* __restrict__ dst, int* __restrict__ deg) {
    int e = blockIdx.x * blockDim.x + threadIdx.x;
    if (e < NE) atomicAdd(&deg[dst[e]], 1);
}

__global__ void k_scan(const int* __restrict__ deg, int n, int* __restrict__ row) {
    __shared__ int part[1024];
    int t = threadIdx.x;
    int chunk = (n + 1023) / 1024;
    int s0 = t * chunk, s1 = min(s0 + chunk, n);
    int sum = 0;
    for (int i = s0; i < s1; i++) sum += deg[i];
    part[t] = sum;
    __syncthreads();
    for (int d = 1; d < 1024; d <<= 1) {
        int v = 0;
        if (t >= d) v = part[t - d];
        __syncthreads();
        if (t >= d) part[t] += v;
        __syncthreads();
    }
    int excl = (t == 0) ? 0 : part[t - 1];
    for (int i = s0; i < s1; i++) { row[i] = excl; excl += deg[i]; }
    if (t == 1023) row[n] = excl;
}

__global__ void k_scatter(const int* __restrict__ src, const int* __restrict__ dst,
                          const int* __restrict__ row, int* __restrict__ cur,
                          int* __restrict__ col) {
    int e = blockIdx.x * blockDim.x + threadIdx.x;
    if (e >= NE) return;
    int d = dst[e];
    int p = row[d] + atomicAdd(&cur[d], 1);
    col[p] = src[e];
}

// ---------------- aggregation: warp per destination node ------------------------
__global__ void k_agg(const int* __restrict__ rowp, const int* __restrict__ col,
                      const float* __restrict__ src, float* __restrict__ dst, int n) {
    int warp = (blockIdx.x * blockDim.x + threadIdx.x) >> 5;
    int lane = threadIdx.x & 31;
    if (warp >= n) return;
    int s = rowp[warp], e = rowp[warp + 1];
    float4 acc = make_float4(0.f, 0.f, 0.f, 0.f);
    for (int j = s; j < e; j += 32) {
        int m = min(32, e - j);
        int idx = (lane < m) ? col[j + lane] : 0;
        for (int t = 0; t < m; t++) {
            int sidx = __shfl_sync(0xffffffffu, idx, t);
            float4 v = ((const float4*)(src + (size_t)sidx * HD))[lane];
            acc.x += v.x; acc.y += v.y; acc.z += v.z; acc.w += v.w;
        }
    }
    ((float4*)(dst + (size_t)warp * HD))[lane] = acc;
}

// ---------------- weight prep: WcT[k][h] = k<128 ? Wrel[h][k] : Wroot[h][k-128] --
__global__ void k_prepW(const float* __restrict__ Wrel, const float* __restrict__ Wroot,
                        float* __restrict__ out) {
    int idx = blockIdx.x * blockDim.x + threadIdx.x;
    if (idx >= 256 * HD) return;
    int k = idx >> 7, h = idx & 127;
    out[idx] = (k < HD) ? Wrel[h * HD + k] : Wroot[h * HD + (k - HD)];
}

// ---------------- fused GEMM: out = relu([A1|A2] @ WcT + bias), + BN stats ------
#define GTM 128
#define GKB 16
#define GAPAD 132   // GTM+4: keeps 16B alignment, limits store conflicts

__global__ __launch_bounds__(256, 2)
void k_gemm(const float* __restrict__ A1, const float* __restrict__ A2,
            const float* __restrict__ WcT, const float* __restrict__ bias,
            float* __restrict__ out, float* __restrict__ stats, int n) {
    __shared__ float As[GKB * GAPAD];
    __shared__ float Ws[GKB * 128];
    int tid = threadIdx.x;
    int row0 = blockIdx.x * GTM;
    int warp = tid >> 5, lane = tid & 31;
    int warpR = warp & 3, warpC = warp >> 2;           // 4 x 2 warps
    int r0 = warpR * 32 + (lane >> 3) * 8;             // 8 rows per thread
    int c0 = warpC * 64 + (lane & 7) * 8;              // 8 cols per thread
    int rg = warpR * 4 + (lane >> 3);                  // row-group id 0..15

    float acc[8][8];
#pragma unroll
    for (int i = 0; i < 8; i++)
#pragma unroll
        for (int j = 0; j < 8; j++) acc[i][j] = 0.f;

    for (int ch = 0; ch < 16; ch++) {
        const float* A = (ch < 8) ? A1 : A2;
        int kbase = (ch & 7) * GKB;
        __syncthreads();
        // load A tile transposed: As[kk][r]
#pragma unroll
        for (int i = 0; i < 2; i++) {
            int lin = tid + i * 256;     // 0..511
            int r = lin >> 2;            // 0..127
            int k4 = lin & 3;            // 0..3
            float4 v = make_float4(0.f, 0.f, 0.f, 0.f);
            int grow = row0 + r;
            if (grow < n) v = *(const float4*)(A + (size_t)grow * HD + kbase + k4 * 4);
            As[(k4 * 4 + 0) * GAPAD + r] = v.x;
            As[(k4 * 4 + 1) * GAPAD + r] = v.y;
            As[(k4 * 4 + 2) * GAPAD + r] = v.z;
            As[(k4 * 4 + 3) * GAPAD + r] = v.w;
        }
        // load W tile: Ws[kk][h]
#pragma unroll
        for (int i = 0; i < 2; i++) {
            int lin = tid + i * 256;
            ((float4*)Ws)[lin] = ((const float4*)(WcT + ch * GKB * 128))[lin];
        }
        __syncthreads();
#pragma unroll
        for (int kk = 0; kk < GKB; kk++) {
            float a[8], w[8];
            *(float4*)&a[0] = *(float4*)&As[kk * GAPAD + r0];
            *(float4*)&a[4] = *(float4*)&As[kk * GAPAD + r0 + 4];
            *(float4*)&w[0] = *(float4*)&Ws[kk * 128 + c0];
            *(float4*)&w[4] = *(float4*)&Ws[kk * 128 + c0 + 4];
#pragma unroll
            for (int i = 0; i < 8; i++)
#pragma unroll
                for (int j = 0; j < 8; j++) acc[i][j] += a[i] * w[j];
        }
    }

    // epilogue: bias + relu + store + per-channel stats
    float bv[8];
    *(float4*)&bv[0] = *(const float4*)(bias + c0);
    *(float4*)&bv[4] = *(const float4*)(bias + c0 + 4);
    float s[8], q[8];
#pragma unroll
    for (int j = 0; j < 8; j++) { s[j] = 0.f; q[j] = 0.f; }
#pragma unroll
    for (int i = 0; i < 8; i++) {
        int grow = row0 + r0 + i;
        if (grow < n) {
            float o[8];
#pragma unroll
            for (int j = 0; j < 8; j++) {
                o[j] = fmaxf(acc[i][j] + bv[j], 0.f);
                s[j] += o[j];
                q[j] += o[j] * o[j];
            }
            *(float4*)(out + (size_t)grow * HD + c0)     = make_float4(o[0], o[1], o[2], o[3]);
            *(float4*)(out + (size_t)grow * HD + c0 + 4) = make_float4(o[4], o[5], o[6], o[7]);
        }
    }
    // reduce stats over the 16 row groups (reuse As: 16*128 = 2048 <= 2112)
    __syncthreads();
#pragma unroll
    for (int j = 0; j < 8; j++) As[rg * 128 + c0 + j] = s[j];
    __syncthreads();
    if (tid < 128) {
        float tt = 0.f;
#pragma unroll
        for (int g = 0; g < 16; g++) tt += As[g * 128 + tid];
        atomicAdd(&stats[tid], tt);
    }
    __syncthreads();
#pragma unroll
    for (int j = 0; j < 8; j++) As[rg * 128 + c0 + j] = q[j];
    __syncthreads();
    if (tid < 128) {
        float tt = 0.f;
#pragma unroll
        for (int g = 0; g < 16; g++) tt += As[g * 128 + tid];
        atomicAdd(&stats[HD + tid], tt);
    }
}

// ---------------- BN apply ------------------------------------------------------
__global__ void k_bn(const float* __restrict__ in, float* __restrict__ out,
                     const float* __restrict__ stats, const float* __restrict__ gam,
                     const float* __restrict__ bet, int n) {
    int idx = blockIdx.x * blockDim.x + threadIdx.x;
    int total = n * (HD / 4);
    if (idx >= total) return;
    int c4 = idx & 31;
    float4 v = ((const float4*)in)[idx];
    float o[4];
    float vv[4] = {v.x, v.y, v.z, v.w};
    float inv_n = 1.f / (float)n;
#pragma unroll
    for (int t = 0; t < 4; t++) {
        int c = c4 * 4 + t;
        float m = stats[c] * inv_n;
        float var = stats[HD + c] * inv_n - m * m;
        float rstd = rsqrtf(fmaxf(var, 0.f) + BN_EPS);
        o[t] = (vv[t] - m) * rstd * gam[c] + bet[c];
    }
    ((float4*)out)[idx] = make_float4(o[0], o[1], o[2], o[3]);
}

// ---------------- pooling (deterministic sequential per group) ------------------
__global__ void k_pool(const float* __restrict__ xu, const float* __restrict__ xi,
                       const int* __restrict__ su, const int* __restrict__ si,
                       float* __restrict__ feats) {
    int g = blockIdx.x, c = threadIdx.x;
    float acc = 0.f;
    int u0 = su[g], u1 = su[g + 1];
    int i0 = si[g], i1 = si[g + 1];
    for (int r = u0; r < u1; r++) acc += xu[(size_t)r * HD + c];
    for (int r = i0; r < i1; r++) acc += xi[(size_t)r * HD + c];
    float cnt = (float)((u1 - u0) + (i1 - i0));
    if (cnt < 1.f) cnt = 1.f;
    feats[(size_t)g * HD + c] = acc / cnt;
}

// ---------------- per-layer classifier heads ------------------------------------
__global__ void k_logits(const float* __restrict__ feats, const float* __restrict__ fcW,
                         const float* __restrict__ fcb, float* __restrict__ logits) {
    int idx = blockIdx.x * blockDim.x + threadIdx.x;
    if (idx >= NL * NG * NC) return;
    int l = idx / (NG * NC);
    int g = (idx / NC) % NG;
    int c = idx % NC;
    const float* f = feats + ((size_t)l * NG + g) * HD;
    const float* w = fcW + ((size_t)l * NC + c) * HD;
    float sum = fcb[l * NC + c];
#pragma unroll
    for (int k = 0; k < HD; k += 4) {
        float4 a = *(const float4*)(f + k);
        float4 b = *(const float4*)(w + k);
        sum += a.x * b.x + a.y * b.y + a.z * b.z + a.w * b.w;
    }
    logits[idx] = sum;
}

// ---------------- host orchestration -------------------------------------------
extern "C" void kernel_launch(void* const* d_in, const int* in_sizes, int n_in,
                              void* d_out, int out_size) {
    const float* x_user    = (const float*)d_in[0];
    const float* x_item    = (const float*)d_in[1];
    const int*   e_u2i     = (const int*)d_in[2];   // [2][NE]: row0 src(users), row1 dst(items)
    const int*   e_i2u     = (const int*)d_in[3];   // [2][NE]: row0 src(items), row1 dst(users)
    const int*   b_user    = (const int*)d_in[4];
    const int*   b_item    = (const int*)d_in[5];
    const float* Wrel_u2i  = (const float*)d_in[6];
    const float* Wroot_u2i = (const float*)d_in[7];
    const float* b_u2i     = (const float*)d_in[8];
    const float* Wrel_i2u  = (const float*)d_in[9];
    const float* Wroot_i2u = (const float*)d_in[10];
    const float* b_i2u     = (const float*)d_in[11];
    const float* bn_g_user = (const float*)d_in[12];
    const float* bn_b_user = (const float*)d_in[13];
    const float* bn_g_item = (const float*)d_in[14];
    const float* bn_b_item = (const float*)d_in[15];
    const float* fc_W      = (const float*)d_in[16];
    const float* fc_b      = (const float*)d_in[17];

    float* out   = (float*)d_out;
    float* feats = out + NL * NG * NC;   // logits first, then feats

    // resolve scratch symbol addresses (host-side, capture-time only; free at replay)
    float *xu, *xi, *aggu, *aggi, *newu, *newi, *stats, *WcTu, *WcTi;
    int *rowi, *rowu, *col_u2i, *col_i2u, *deg, *cur, *su, *si;
    cudaGetSymbolAddress((void**)&xu, g_xu);
    cudaGetSymbolAddress((void**)&xi, g_xi);
    cudaGetSymbolAddress((void**)&aggu, g_aggu);
    cudaGetSymbolAddress((void**)&aggi, g_aggi);
    cudaGetSymbolAddress((void**)&newu, g_newu);
    cudaGetSymbolAddress((void**)&newi, g_newi);
    cudaGetSymbolAddress((void**)&stats, g_stats);
    cudaGetSymbolAddress((void**)&WcTu, g_WcTu);
    cudaGetSymbolAddress((void**)&WcTi, g_WcTi);
    cudaGetSymbolAddress((void**)&rowi, g_rowi);
    cudaGetSymbolAddress((void**)&rowu, g_rowu);
    cudaGetSymbolAddress((void**)&col_u2i, g_col_u2i);
    cudaGetSymbolAddress((void**)&col_i2u, g_col_i2u);
    cudaGetSymbolAddress((void**)&deg, g_deg);
    cudaGetSymbolAddress((void**)&cur, g_cur);
    cudaGetSymbolAddress((void**)&su, g_su);
    cudaGetSymbolAddress((void**)&si, g_si);

    const int T = 256;

    // init
    k_copy4<<<CDIV(NU*HD/4, T), T>>>(xu, x_user, NU*HD/4);
    k_copy4<<<CDIV(NI*HD/4, T), T>>>(xi, x_item, NI*HD/4);
    k_zero_f<<<CDIV(NL*2*2*HD, T), T>>>(stats, NL*2*2*HD);
    k_offsets<<<CDIV(NG+1, 128), 128>>>(b_user, NU, su);
    k_offsets<<<CDIV(NG+1, 128), 128>>>(b_item, NI, si);

    // CSR for u2i (dst = items)
    k_zero_i<<<CDIV(NI, T), T>>>(deg, NI);
    k_hist<<<CDIV(NE, T), T>>>(e_u2i + NE, deg);
    k_scan<<<1, 1024>>>(deg, NI, rowi);
    k_zero_i<<<CDIV(NI, T), T>>>(cur, NI);
    k_scatter<<<CDIV(NE, T), T>>>(e_u2i, e_u2i + NE, rowi, cur, col_u2i);

    // CSR for i2u (dst = users)
    k_zero_i<<<CDIV(NU, T), T>>>(deg, NU);
    k_hist<<<CDIV(NE, T), T>>>(e_i2u + NE, deg);
    k_scan<<<1, 1024>>>(deg, NU, rowu);
    k_zero_i<<<CDIV(NU, T), T>>>(cur, NU);
    k_scatter<<<CDIV(NE, T), T>>>(e_i2u, e_i2u + NE, rowu, cur, col_i2u);

    for (int l = 0; l < NL; l++) {
        k_prepW<<<CDIV(256*HD, T), T>>>(Wrel_u2i + (size_t)l*HD*HD, Wroot_u2i + (size_t)l*HD*HD, WcTi);
        k_prepW<<<CDIV(256*HD, T), T>>>(Wrel_i2u + (size_t)l*HD*HD, Wroot_i2u + (size_t)l*HD*HD, WcTu);

        k_agg<<<CDIV(NI*32, T), T>>>(rowi, col_u2i, xu, aggi, NI);
        k_agg<<<CDIV(NU*32, T), T>>>(rowu, col_i2u, xi, aggu, NU);

        float* stats_u = stats + (size_t)(l*2 + 0) * 2 * HD;
        float* stats_i = stats + (size_t)(l*2 + 1) * 2 * HD;

        k_gemm<<<CDIV(NI, GTM), 256>>>(aggi, xi, WcTi, b_u2i + (size_t)l*HD, newi, stats_i, NI);
        k_gemm<<<CDIV(NU, GTM), 256>>>(aggu, xu, WcTu, b_i2u + (size_t)l*HD, newu, stats_u, NU);

        k_bn<<<CDIV(NU*HD/4, T), T>>>(newu, xu, stats_u, bn_g_user, bn_b_user, NU);
        k_bn<<<CDIV(NI*HD/4, T), T>>>(newi, xi, stats_i, bn_g_item, bn_b_item, NI);

        k_pool<<<NG, HD>>>(xu, xi, su, si, feats + (size_t)l*NG*HD);
    }

    k_logits<<<CDIV(NL*NG*NC, T), T>>>(feats, fc_W, fc_b, out);
}

// round 4
// speedup vs baseline: 1.4491x; 1.4491x over previous
#include <cuda_runtime.h>
#include <cuda_bf16.h>
#include <cstdint>
#include <math.h>

#define NU 50000
#define NI 50000
#define HD 128
#define NE 800000
#define NG 512
#define NC 16
#define NL 3
#define BN_EPS 1e-5f

#define CDIV(a,b) (((a)+(b)-1)/(b))

// ---------------- scratch (static device globals; no runtime alloc) -------------
__device__ float g_xu[(size_t)NU*HD];
__device__ float g_xi[(size_t)NI*HD];
__device__ float g_aggu[(size_t)NU*HD];
__device__ float g_aggi[(size_t)NI*HD];
__device__ float g_newu[(size_t)NU*HD];
__device__ float g_newi[(size_t)NI*HD];
__device__ int   g_rowi[NI+1];
__device__ int   g_rowu[NU+1];
__device__ int   g_col_u2i[NE];
__device__ int   g_col_i2u[NE];
__device__ int   g_deg[NU];
__device__ int   g_cur[NU];
__device__ float g_stats[NL*2*2*HD];   // [layer][type][sum|sumsq][ch]
__device__ int   g_su[NG+1];
__device__ int   g_si[NG+1];

// =================== helpers ====================================================
__device__ __forceinline__ uint32_t smem_u32(const void* p) {
    uint32_t a;
    asm("{ .reg .u64 t; cvta.to.shared.u64 t, %1; cvt.u32.u64 %0, t; }" : "=r"(a) : "l"(p));
    return a;
}
__device__ __forceinline__ void ldsm4(uint32_t* r, uint32_t addr) {
    asm volatile("ldmatrix.sync.aligned.m8n8.x4.shared.b16 {%0,%1,%2,%3}, [%4];"
        : "=r"(r[0]), "=r"(r[1]), "=r"(r[2]), "=r"(r[3]) : "r"(addr));
}
__device__ __forceinline__ void mma16816(float* d, const uint32_t* a, const uint32_t* b) {
    asm volatile(
        "mma.sync.aligned.m16n8k16.row.col.f32.bf16.bf16.f32 "
        "{%0,%1,%2,%3}, {%4,%5,%6,%7}, {%8,%9}, {%0,%1,%2,%3};"
        : "+f"(d[0]), "+f"(d[1]), "+f"(d[2]), "+f"(d[3])
        : "r"(a[0]), "r"(a[1]), "r"(a[2]), "r"(a[3]), "r"(b[0]), "r"(b[1]));
}
__device__ __forceinline__ void split2(float a, float b, uint32_t& hi, uint32_t& lo) {
    __nv_bfloat16 ah = __float2bfloat16(a);
    __nv_bfloat16 bh = __float2bfloat16(b);
    __nv_bfloat16 al = __float2bfloat16(a - __bfloat162float(ah));
    __nv_bfloat16 bl = __float2bfloat16(b - __bfloat162float(bh));
    hi = (uint32_t)__bfloat16_as_ushort(ah) | ((uint32_t)__bfloat16_as_ushort(bh) << 16);
    lo = (uint32_t)__bfloat16_as_ushort(al) | ((uint32_t)__bfloat16_as_ushort(bl) << 16);
}

// ---------------- small utility kernels ----------------------------------------
__global__ void k_copy4(float* __restrict__ dst, const float* __restrict__ src, int n4) {
    int i = blockIdx.x * blockDim.x + threadIdx.x;
    if (i < n4) ((float4*)dst)[i] = ((const float4*)src)[i];
}
__global__ void k_zero_f(float* p, int n) {
    int i = blockIdx.x * blockDim.x + threadIdx.x;
    if (i < n) p[i] = 0.f;
}
__global__ void k_zero_i(int* p, int n) {
    int i = blockIdx.x * blockDim.x + threadIdx.x;
    if (i < n) p[i] = 0;
}
__global__ void k_offsets(const int* __restrict__ batch, int n, int* __restrict__ off) {
    int g = blockIdx.x * blockDim.x + threadIdx.x;
    if (g > NG) return;
    int lo = 0, hi = n;
    while (lo < hi) { int mid = (lo + hi) >> 1; if (batch[mid] < g) lo = mid + 1; else hi = mid; }
    off[g] = lo;
}

// ---------------- CSR build -----------------------------------------------------
__global__ void k_hist(const int* __restrict__ dst, int* __restrict__ deg) {
    int e = blockIdx.x * blockDim.x + threadIdx.x;
    if (e < NE) atomicAdd(&deg[dst[e]], 1);
}
__global__ void k_scan(const int* __restrict__ deg, int n, int* __restrict__ row) {
    __shared__ int part[1024];
    int t = threadIdx.x;
    int chunk = (n + 1023) / 1024;
    int s0 = t * chunk, s1 = min(s0 + chunk, n);
    int sum = 0;
    for (int i = s0; i < s1; i++) sum += deg[i];
    part[t] = sum;
    __syncthreads();
    for (int d = 1; d < 1024; d <<= 1) {
        int v = 0;
        if (t >= d) v = part[t - d];
        __syncthreads();
        if (t >= d) part[t] += v;
        __syncthreads();
    }
    int excl = (t == 0) ? 0 : part[t - 1];
    for (int i = s0; i < s1; i++) { row[i] = excl; excl += deg[i]; }
    if (t == 1023) row[n] = excl;
}
__global__ void k_scatter(const int* __restrict__ src, const int* __restrict__ dst,
                          const int* __restrict__ row, int* __restrict__ cur,
                          int* __restrict__ col) {
    int e = blockIdx.x * blockDim.x + threadIdx.x;
    if (e >= NE) return;
    int d = dst[e];
    int p = row[d] + atomicAdd(&cur[d], 1);
    col[p] = src[e];
}

// ---------------- aggregation: warp per destination node ------------------------
__global__ void k_agg(const int* __restrict__ rowp, const int* __restrict__ col,
                      const float* __restrict__ src, float* __restrict__ dst, int n) {
    int warp = (blockIdx.x * blockDim.x + threadIdx.x) >> 5;
    int lane = threadIdx.x & 31;
    if (warp >= n) return;
    int s = rowp[warp], e = rowp[warp + 1];
    float4 acc = make_float4(0.f, 0.f, 0.f, 0.f);
    for (int j = s; j < e; j += 32) {
        int m = min(32, e - j);
        int idx = (lane < m) ? col[j + lane] : 0;
        for (int t = 0; t < m; t++) {
            int sidx = __shfl_sync(0xffffffffu, idx, t);
            float4 v = ((const float4*)(src + (size_t)sidx * HD))[lane];
            acc.x += v.x; acc.y += v.y; acc.z += v.z; acc.w += v.w;
        }
    }
    ((float4*)(dst + (size_t)warp * HD))[lane] = acc;
}

// ============== mma.sync GEMM: relu([agg|x] @ [Wrel|Wroot]^T + b) + BN stats ====
// Per CTA: M=128, N=128, K=256 (two K=128 halves).
// bf16 split: D = Ah*Bh + Al*Bh + Ah*Bl, fp32 accumulate in registers.
#define A_HI 0
#define A_LO 32768
#define B_HI 65536
#define B_LO 98304
#define SMF_STRIDE 136
#define SSUM_OFF 100352
#define SSQ_OFF  100864
#define GEMM_SMEM 131072

__global__ __launch_bounds__(256, 1)
void k_gemm_mma(const float* __restrict__ Aagg, const float* __restrict__ Ax,
                const float* __restrict__ Wrel, const float* __restrict__ Wroot,
                const float* __restrict__ bias, float* __restrict__ out,
                float* __restrict__ stats, int n)
{
    extern __shared__ __align__(128) char smem[];
    uint32_t sb = smem_u32(smem);
    int tid = threadIdx.x;
    int lane = tid & 31, warp = tid >> 5;
    int warpM = warp & 3, warpN = warp >> 2;
    int row0 = blockIdx.x * 128;

    // per-lane ldmatrix addressing constants
    int mi = lane >> 3;           // matrix index within x4
    int lr = lane & 7;            // row within 8x8 matrix
    // A: matrices ordered {m0-7,k0-7},{m8-15,k0-7},{m0-7,k8-15},{m8-15,k8-15}
    int a_kmi = mi >> 1;
    uint32_t a_off[2], a_xor[2];
#pragma unroll
    for (int mt = 0; mt < 2; mt++) {
        int r = warpM * 32 + mt * 16 + (mi & 1) * 8 + lr;
        a_off[mt] = r * 256;
        a_xor[mt] = r & 7;
    }
    // B: per pair jj, matrices {n0-7,k0-7},{n0-7,k8-15},{n8-15,k0-7},{n8-15,k8-15}
    int b_kmi = mi & 1;
    uint32_t b_off[4], b_xor[4];
#pragma unroll
    for (int jj = 0; jj < 4; jj++) {
        int r = warpN * 64 + jj * 16 + (mi >> 1) * 8 + lr;
        b_off[jj] = r * 256;
        b_xor[jj] = r & 7;
    }

    float acc[2][8][4];
#pragma unroll
    for (int mt = 0; mt < 2; mt++)
#pragma unroll
        for (int j = 0; j < 8; j++)
#pragma unroll
            for (int t = 0; t < 4; t++) acc[mt][j][t] = 0.f;

    for (int h = 0; h < 2; h++) {
        if (h) __syncthreads();               // prior MMAs consumed SMEM
        const float* As = h ? Ax : Aagg;
        const float* Bs = h ? Wroot : Wrel;
        // fill A tile: 128 rows x 128 k fp32 -> bf16 hi/lo, chunk-swizzled
#pragma unroll
        for (int i = 0; i < 8; i++) {
            int lin = tid + i * 256;          // chunk id 0..2047
            int r = lin >> 4, c = lin & 15;   // row, 16B chunk (8 bf16 = 8 k)
            int gr = row0 + r;
            float4 v0 = make_float4(0.f,0.f,0.f,0.f), v1 = v0;
            if (gr < n) {
                v0 = *(const float4*)(As + (size_t)gr * HD + c * 8);
                v1 = *(const float4*)(As + (size_t)gr * HD + c * 8 + 4);
            }
            uint32_t h0,l0,h1,l1,h2,l2,h3,l3;
            split2(v0.x, v0.y, h0, l0); split2(v0.z, v0.w, h1, l1);
            split2(v1.x, v1.y, h2, l2); split2(v1.z, v1.w, h3, l3);
            int off = r * 256 + ((c ^ (r & 7)) << 4);
            *(uint4*)(smem + A_HI + off) = make_uint4(h0, h1, h2, h3);
            *(uint4*)(smem + A_LO + off) = make_uint4(l0, l1, l2, l3);
        }
        // fill B tile: 128 n-rows x 128 k
#pragma unroll
        for (int i = 0; i < 8; i++) {
            int lin = tid + i * 256;
            int r = lin >> 4, c = lin & 15;
            float4 v0 = *(const float4*)(Bs + (size_t)r * HD + c * 8);
            float4 v1 = *(const float4*)(Bs + (size_t)r * HD + c * 8 + 4);
            uint32_t h0,l0,h1,l1,h2,l2,h3,l3;
            split2(v0.x, v0.y, h0, l0); split2(v0.z, v0.w, h1, l1);
            split2(v1.x, v1.y, h2, l2); split2(v1.z, v1.w, h3, l3);
            int off = r * 256 + ((c ^ (r & 7)) << 4);
            *(uint4*)(smem + B_HI + off) = make_uint4(h0, h1, h2, h3);
            *(uint4*)(smem + B_LO + off) = make_uint4(l0, l1, l2, l3);
        }
        __syncthreads();

#pragma unroll
        for (int p = 0; p < 3; p++) {
            uint32_t bA = sb + ((p == 1) ? A_LO : A_HI);
            uint32_t bB = sb + ((p == 2) ? B_LO : B_HI);
#pragma unroll
            for (int ks = 0; ks < 8; ks++) {
                uint32_t afr[2][4];
#pragma unroll
                for (int mt = 0; mt < 2; mt++) {
                    uint32_t ck = (uint32_t)((ks << 1) | a_kmi) ^ a_xor[mt];
                    ldsm4(afr[mt], bA + a_off[mt] + (ck << 4));
                }
                uint32_t bfr[8][2];
#pragma unroll
                for (int jj = 0; jj < 4; jj++) {
                    uint32_t q[4];
                    uint32_t ck = (uint32_t)((ks << 1) | b_kmi) ^ b_xor[jj];
                    ldsm4(q, bB + b_off[jj] + (ck << 4));
                    bfr[2*jj][0] = q[0]; bfr[2*jj][1] = q[1];
                    bfr[2*jj+1][0] = q[2]; bfr[2*jj+1][1] = q[3];
                }
#pragma unroll
                for (int mt = 0; mt < 2; mt++)
#pragma unroll
                    for (int j = 0; j < 8; j++)
                        mma16816(acc[mt][j], afr[mt], bfr[j]);
            }
        }
    }
    __syncthreads();   // MMAs done; SMEM reusable

    // stage accums into padded SMEM (stride 136 floats -> conflict-free)
    float* smF = (float*)smem;
    float* ssum = (float*)(smem + SSUM_OFF);
    float* ssq  = (float*)(smem + SSQ_OFF);
    if (tid < 128) { ssum[tid] = 0.f; ssq[tid] = 0.f; }
#pragma unroll
    for (int mt = 0; mt < 2; mt++) {
        int r0 = warpM * 32 + mt * 16 + (lane >> 2);
        int c  = warpN * 64 + (lane & 3) * 2;
#pragma unroll
        for (int j = 0; j < 8; j++) {
            int cc = c + j * 8;
            *(float2*)&smF[r0 * SMF_STRIDE + cc]       = make_float2(acc[mt][j][0], acc[mt][j][1]);
            *(float2*)&smF[(r0 + 8) * SMF_STRIDE + cc] = make_float2(acc[mt][j][2], acc[mt][j][3]);
        }
    }
    __syncthreads();

    // bias + relu + coalesced store + BN stats
    {
        int c4 = tid & 31, rg = tid >> 5;
        float4 bv = *(const float4*)(bias + c4 * 4);
        float s0=0,s1=0,s2=0,s3=0,q0=0,q1=0,q2=0,q3=0;
#pragma unroll
        for (int it = 0; it < 16; it++) {
            int r = it * 8 + rg;
            int gr = row0 + r;
            if (gr < n) {
                float4 v = *(float4*)&smF[r * SMF_STRIDE + c4 * 4];
                v.x = fmaxf(v.x + bv.x, 0.f);
                v.y = fmaxf(v.y + bv.y, 0.f);
                v.z = fmaxf(v.z + bv.z, 0.f);
                v.w = fmaxf(v.w + bv.w, 0.f);
                *(float4*)(out + (size_t)gr * HD + c4 * 4) = v;
                s0 += v.x; s1 += v.y; s2 += v.z; s3 += v.w;
                q0 += v.x*v.x; q1 += v.y*v.y; q2 += v.z*v.z; q3 += v.w*v.w;
            }
        }
        atomicAdd(&ssum[c4*4+0], s0); atomicAdd(&ssum[c4*4+1], s1);
        atomicAdd(&ssum[c4*4+2], s2); atomicAdd(&ssum[c4*4+3], s3);
        atomicAdd(&ssq[c4*4+0], q0);  atomicAdd(&ssq[c4*4+1], q1);
        atomicAdd(&ssq[c4*4+2], q2);  atomicAdd(&ssq[c4*4+3], q3);
    }
    __syncthreads();
    if (tid < 128) {
        atomicAdd(&stats[tid], ssum[tid]);
        atomicAdd(&stats[HD + tid], ssq[tid]);
    }
}

// ---------------- BN apply ------------------------------------------------------
__global__ void k_bn(const float* __restrict__ in, float* __restrict__ out,
                     const float* __restrict__ stats, const float* __restrict__ gam,
                     const float* __restrict__ bet, int n) {
    int idx = blockIdx.x * blockDim.x + threadIdx.x;
    int total = n * (HD / 4);
    if (idx >= total) return;
    int c4 = idx & 31;
    float4 v = ((const float4*)in)[idx];
    float o[4];
    float vv[4] = {v.x, v.y, v.z, v.w};
    float inv_n = 1.f / (float)n;
#pragma unroll
    for (int t = 0; t < 4; t++) {
        int c = c4 * 4 + t;
        float m = stats[c] * inv_n;
        float var = stats[HD + c] * inv_n - m * m;
        float rstd = rsqrtf(fmaxf(var, 0.f) + BN_EPS);
        o[t] = (vv[t] - m) * rstd * gam[c] + bet[c];
    }
    ((float4*)out)[idx] = make_float4(o[0], o[1], o[2], o[3]);
}

// ---------------- pooling (deterministic sequential per group) ------------------
__global__ void k_pool(const float* __restrict__ xu, const float* __restrict__ xi,
                       const int* __restrict__ su, const int* __restrict__ si,
                       float* __restrict__ feats) {
    int g = blockIdx.x, c = threadIdx.x;
    float acc = 0.f;
    int u0 = su[g], u1 = su[g + 1];
    int i0 = si[g], i1 = si[g + 1];
    for (int r = u0; r < u1; r++) acc += xu[(size_t)r * HD + c];
    for (int r = i0; r < i1; r++) acc += xi[(size_t)r * HD + c];
    float cnt = (float)((u1 - u0) + (i1 - i0));
    if (cnt < 1.f) cnt = 1.f;
    feats[(size_t)g * HD + c] = acc / cnt;
}

// ---------------- per-layer classifier heads ------------------------------------
__global__ void k_logits(const float* __restrict__ feats, const float* __restrict__ fcW,
                         const float* __restrict__ fcb, float* __restrict__ logits) {
    int idx = blockIdx.x * blockDim.x + threadIdx.x;
    if (idx >= NL * NG * NC) return;
    int l = idx / (NG * NC);
    int g = (idx / NC) % NG;
    int c = idx % NC;
    const float* f = feats + ((size_t)l * NG + g) * HD;
    const float* w = fcW + ((size_t)l * NC + c) * HD;
    float sum = fcb[l * NC + c];
#pragma unroll
    for (int k = 0; k < HD; k += 4) {
        float4 a = *(const float4*)(f + k);
        float4 b = *(const float4*)(w + k);
        sum += a.x * b.x + a.y * b.y + a.z * b.z + a.w * b.w;
    }
    logits[idx] = sum;
}

// ---------------- host orchestration -------------------------------------------
extern "C" void kernel_launch(void* const* d_in, const int* in_sizes, int n_in,
                              void* d_out, int out_size) {
    const float* x_user    = (const float*)d_in[0];
    const float* x_item    = (const float*)d_in[1];
    const int*   e_u2i     = (const int*)d_in[2];
    const int*   e_i2u     = (const int*)d_in[3];
    const int*   b_user    = (const int*)d_in[4];
    const int*   b_item    = (const int*)d_in[5];
    const float* Wrel_u2i  = (const float*)d_in[6];
    const float* Wroot_u2i = (const float*)d_in[7];
    const float* b_u2i     = (const float*)d_in[8];
    const float* Wrel_i2u  = (const float*)d_in[9];
    const float* Wroot_i2u = (const float*)d_in[10];
    const float* b_i2u     = (const float*)d_in[11];
    const float* bn_g_user = (const float*)d_in[12];
    const float* bn_b_user = (const float*)d_in[13];
    const float* bn_g_item = (const float*)d_in[14];
    const float* bn_b_item = (const float*)d_in[15];
    const float* fc_W      = (const float*)d_in[16];
    const float* fc_b      = (const float*)d_in[17];

    float* out   = (float*)d_out;
    float* feats = out + NL * NG * NC;

    float *xu, *xi, *aggu, *aggi, *newu, *newi, *stats;
    int *rowi, *rowu, *col_u2i, *col_i2u, *deg, *cur, *su, *si;
    cudaGetSymbolAddress((void**)&xu, g_xu);
    cudaGetSymbolAddress((void**)&xi, g_xi);
    cudaGetSymbolAddress((void**)&aggu, g_aggu);
    cudaGetSymbolAddress((void**)&aggi, g_aggi);
    cudaGetSymbolAddress((void**)&newu, g_newu);
    cudaGetSymbolAddress((void**)&newi, g_newi);
    cudaGetSymbolAddress((void**)&stats, g_stats);
    cudaGetSymbolAddress((void**)&rowi, g_rowi);
    cudaGetSymbolAddress((void**)&rowu, g_rowu);
    cudaGetSymbolAddress((void**)&col_u2i, g_col_u2i);
    cudaGetSymbolAddress((void**)&col_i2u, g_col_i2u);
    cudaGetSymbolAddress((void**)&deg, g_deg);
    cudaGetSymbolAddress((void**)&cur, g_cur);
    cudaGetSymbolAddress((void**)&su, g_su);
    cudaGetSymbolAddress((void**)&si, g_si);

    cudaFuncSetAttribute(k_gemm_mma, cudaFuncAttributeMaxDynamicSharedMemorySize, GEMM_SMEM);

    const int T = 256;

    k_copy4<<<CDIV(NU*HD/4, T), T>>>(xu, x_user, NU*HD/4);
    k_copy4<<<CDIV(NI*HD/4, T), T>>>(xi, x_item, NI*HD/4);
    k_zero_f<<<CDIV(NL*2*2*HD, T), T>>>(stats, NL*2*2*HD);
    k_offsets<<<CDIV(NG+1, 128), 128>>>(b_user, NU, su);
    k_offsets<<<CDIV(NG+1, 128), 128>>>(b_item, NI, si);

    // CSR for u2i (dst = items)
    k_zero_i<<<CDIV(NI, T), T>>>(deg, NI);
    k_hist<<<CDIV(NE, T), T>>>(e_u2i + NE, deg);
    k_scan<<<1, 1024>>>(deg, NI, rowi);
    k_zero_i<<<CDIV(NI, T), T>>>(cur, NI);
    k_scatter<<<CDIV(NE, T), T>>>(e_u2i, e_u2i + NE, rowi, cur, col_u2i);

    // CSR for i2u (dst = users)
    k_zero_i<<<CDIV(NU, T), T>>>(deg, NU);
    k_hist<<<CDIV(NE, T), T>>>(e_i2u + NE, deg);
    k_scan<<<1, 1024>>>(deg, NU, rowu);
    k_zero_i<<<CDIV(NU, T), T>>>(cur, NU);
    k_scatter<<<CDIV(NE, T), T>>>(e_i2u, e_i2u + NE, rowu, cur, col_i2u);

    for (int l = 0; l < NL; l++) {
        k_agg<<<CDIV(NI*32, T), T>>>(rowi, col_u2i, xu, aggi, NI);
        k_agg<<<CDIV(NU*32, T), T>>>(rowu, col_i2u, xi, aggu, NU);

        float* stats_u = stats + (size_t)(l*2 + 0) * 2 * HD;
        float* stats_i = stats + (size_t)(l*2 + 1) * 2 * HD;

        k_gemm_mma<<<CDIV(NI, 128), 256, GEMM_SMEM>>>(
            aggi, xi, Wrel_u2i + (size_t)l*HD*HD, Wroot_u2i + (size_t)l*HD*HD,
            b_u2i + (size_t)l*HD, newi, stats_i, NI);
        k_gemm_mma<<<CDIV(NU, 128), 256, GEMM_SMEM>>>(
            aggu, xu, Wrel_i2u + (size_t)l*HD*HD, Wroot_i2u + (size_t)l*HD*HD,
            b_i2u + (size_t)l*HD, newu, stats_u, NU);

        k_bn<<<CDIV(NU*HD/4, T), T>>>(newu, xu, stats_u, bn_g_user, bn_b_user, NU);
        k_bn<<<CDIV(NI*HD/4, T), T>>>(newi, xi, stats_i, bn_g_item, bn_b_item, NI);

        k_pool<<<NG, HD>>>(xu, xi, su, si, feats + (size_t)l*NG*HD);
    }

    k_logits<<<CDIV(NL*NG*NC, T), T>>>(feats, fc_W, fc_b, out);
}

// round 5
// speedup vs baseline: 1.5832x; 1.0926x over previous
#include <cuda_runtime.h>
#include <cuda_bf16.h>
#include <cstdint>
#include <math.h>

#define NU 50000
#define NI 50000
#define N5 50000
#define HD 128
#define NE 800000
#define NG 512
#define NC 16
#define NL 3
#define BN_EPS 1e-5f

#define CDIV(a,b) (((a)+(b)-1)/(b))

// ---------------- scratch (static device globals; no runtime alloc) -------------
__device__ float g_xu[(size_t)NU*HD];
__device__ float g_xi[(size_t)NI*HD];
__device__ float g_newu[(size_t)NU*HD];
__device__ float g_newi[(size_t)NI*HD];
__device__ float g_aggu[(size_t)NU*HD];
__device__ float g_aggi[(size_t)NI*HD];
__device__ int   g_rowi[NI+1];
__device__ int   g_rowu[NU+1];
__device__ int   g_col_u2i[NE];
__device__ int   g_col_i2u[NE];
__device__ int   g_deg[NU];
__device__ int   g_cur[NU];
__device__ float g_stats[NL*2*2*HD];   // [layer][type(0=user,1=item)][sum|sumsq][ch]
__device__ int   g_su[NG+1];
__device__ int   g_si[NG+1];

// =================== helpers ====================================================
__device__ __forceinline__ uint32_t smem_u32(const void* p) {
    uint32_t a;
    asm("{ .reg .u64 t; cvta.to.shared.u64 t, %1; cvt.u32.u64 %0, t; }" : "=r"(a) : "l"(p));
    return a;
}
__device__ __forceinline__ void ldsm4(uint32_t* r, uint32_t addr) {
    asm volatile("ldmatrix.sync.aligned.m8n8.x4.shared.b16 {%0,%1,%2,%3}, [%4];"
        : "=r"(r[0]), "=r"(r[1]), "=r"(r[2]), "=r"(r[3]) : "r"(addr));
}
__device__ __forceinline__ void mma16816(float* d, const uint32_t* a, const uint32_t* b) {
    asm volatile(
        "mma.sync.aligned.m16n8k16.row.col.f32.bf16.bf16.f32 "
        "{%0,%1,%2,%3}, {%4,%5,%6,%7}, {%8,%9}, {%0,%1,%2,%3};"
        : "+f"(d[0]), "+f"(d[1]), "+f"(d[2]), "+f"(d[3])
        : "r"(a[0]), "r"(a[1]), "r"(a[2]), "r"(a[3]), "r"(b[0]), "r"(b[1]));
}
__device__ __forceinline__ void split2(float a, float b, uint32_t& hi, uint32_t& lo) {
    __nv_bfloat16 ah = __float2bfloat16(a);
    __nv_bfloat16 bh = __float2bfloat16(b);
    __nv_bfloat16 al = __float2bfloat16(a - __bfloat162float(ah));
    __nv_bfloat16 bl = __float2bfloat16(b - __bfloat162float(bh));
    hi = (uint32_t)__bfloat16_as_ushort(ah) | ((uint32_t)__bfloat16_as_ushort(bh) << 16);
    lo = (uint32_t)__bfloat16_as_ushort(al) | ((uint32_t)__bfloat16_as_ushort(bl) << 16);
}

// ---------------- small utility kernels ----------------------------------------
__global__ void k_zero_f(float* p, int n) {
    int i = blockIdx.x * blockDim.x + threadIdx.x;
    if (i < n) p[i] = 0.f;
}
__global__ void k_zero_i(int* p, int n) {
    int i = blockIdx.x * blockDim.x + threadIdx.x;
    if (i < n) p[i] = 0;
}
__global__ void k_offsets(const int* __restrict__ batch, int n, int* __restrict__ off) {
    int g = blockIdx.x * blockDim.x + threadIdx.x;
    if (g > NG) return;
    int lo = 0, hi = n;
    while (lo < hi) { int mid = (lo + hi) >> 1; if (batch[mid] < g) lo = mid + 1; else hi = mid; }
    off[g] = lo;
}

// ---------------- CSR build -----------------------------------------------------
__global__ void k_hist(const int* __restrict__ dst, int* __restrict__ deg) {
    int e = blockIdx.x * blockDim.x + threadIdx.x;
    if (e < NE) atomicAdd(&deg[dst[e]], 1);
}
__global__ void k_scan(const int* __restrict__ deg, int n, int* __restrict__ row) {
    __shared__ int part[1024];
    int t = threadIdx.x;
    int chunk = (n + 1023) / 1024;
    int s0 = t * chunk, s1 = min(s0 + chunk, n);
    int sum = 0;
    for (int i = s0; i < s1; i++) sum += deg[i];
    part[t] = sum;
    __syncthreads();
    for (int d = 1; d < 1024; d <<= 1) {
        int v = 0;
        if (t >= d) v = part[t - d];
        __syncthreads();
        if (t >= d) part[t] += v;
        __syncthreads();
    }
    int excl = (t == 0) ? 0 : part[t - 1];
    for (int i = s0; i < s1; i++) { row[i] = excl; excl += deg[i]; }
    if (t == 1023) row[n] = excl;
}
__global__ void k_scatter(const int* __restrict__ src, const int* __restrict__ dst,
                          const int* __restrict__ row, int* __restrict__ cur,
                          int* __restrict__ col) {
    int e = blockIdx.x * blockDim.x + threadIdx.x;
    if (e >= NE) return;
    int d = dst[e];
    int p = row[d] + atomicAdd(&cur[d], 1);
    col[p] = src[e];
}

// ---------------- combined aggregation: both relations in one launch ------------
__device__ __forceinline__ void agg_one(const int* __restrict__ rowp,
                                        const int* __restrict__ col,
                                        const float* __restrict__ src,
                                        float* __restrict__ dst, int node, int lane) {
    int s = rowp[node], e = rowp[node + 1];
    float4 acc = make_float4(0.f, 0.f, 0.f, 0.f);
    for (int j = s; j < e; j += 32) {
        int m = min(32, e - j);
        int idx = (lane < m) ? col[j + lane] : 0;
        for (int t = 0; t < m; t++) {
            int sidx = __shfl_sync(0xffffffffu, idx, t);
            float4 v = ((const float4*)(src + (size_t)sidx * HD))[lane];
            acc.x += v.x; acc.y += v.y; acc.z += v.z; acc.w += v.w;
        }
    }
    ((float4*)(dst + (size_t)node * HD))[lane] = acc;
}

__global__ void k_agg2(const int* __restrict__ rowi, const int* __restrict__ coli,
                       const float* __restrict__ srcU, float* __restrict__ dstI,
                       const int* __restrict__ rowu, const int* __restrict__ colu,
                       const float* __restrict__ srcI, float* __restrict__ dstU) {
    int w = (blockIdx.x * blockDim.x + threadIdx.x) >> 5;
    int lane = threadIdx.x & 31;
    if (w < NI)            agg_one(rowi, coli, srcU, dstI, w, lane);
    else if (w < NI + NU)  agg_one(rowu, colu, srcI, dstU, w - NI, lane);
}

// ============== mma.sync GEMM, BN fused lazily into the A-fill ==================
// out = relu([affS(agg)|affD(x)] @ [Wrel|Wroot]^T + bias); accumulate BN stats.
// affS(agg)[i,k] = saS[k]*agg[i,k] + deg_i*sbS[k]   (BN of source type, prev layer)
// affD(x)[i,k]   = saD[k]*x[i,k]   + sbD[k]         (BN of dest type, prev layer)
#define A_HI 0
#define A_LO 32768
#define B_HI 65536
#define B_LO 98304
#define SMF_STRIDE 136
#define SSUM_OFF 100352
#define SSQ_OFF  100864
#define AFF_OFF  131072
#define GEMM_SMEM (131072 + 2560)

struct GemmSide {
    const float* agg;     // aggregated raw source features [N5, HD]
    const float* xprev;   // raw dest features, prev layer [N5, HD]
    const float* wrel;    // [HD, HD]
    const float* wroot;   // [HD, HD]
    const float* bias;    // [HD]
    float*       out;     // raw relu out [N5, HD]
    float*       statsAcc;// [2*HD] sum|sumsq, this layer
    const int*   rowp;    // [N5+1] (for deg)
    const float* statsS;  // prev-layer stats of SOURCE type
    const float* gS; const float* bS;
    const float* statsD;  // prev-layer stats of DEST type
    const float* gD; const float* bD;
};

__global__ __launch_bounds__(256, 1)
void k_gemm2(GemmSide SI, GemmSide SU, int nblk0, int use_affine)
{
    extern __shared__ __align__(128) char smem[];
    uint32_t sb = smem_u32(smem);
    int tid = threadIdx.x;
    int lane = tid & 31, warp = tid >> 5;
    int warpM = warp & 3, warpN = warp >> 2;

    const GemmSide& S = (blockIdx.x < nblk0) ? SI : SU;
    int row0 = ((blockIdx.x < nblk0) ? blockIdx.x : blockIdx.x - nblk0) * 128;

    // affine coefficients + per-row degree into dedicated smem region
    float* affSa = (float*)(smem + AFF_OFF);         // [128]
    float* affSb = affSa + 128;
    float* affDa = affSb + 128;
    float* affDb = affDa + 128;
    float* degf  = affDb + 128;                      // [128]
    if (tid < 128) {
        float sa0 = 1.f, sb0 = 0.f, sa1 = 1.f, sb1 = 0.f;
        if (use_affine) {
            const float invN = 1.f / (float)N5;
            float m = S.statsS[tid] * invN;
            float var = S.statsS[HD + tid] * invN - m * m;
            float a = S.gS[tid] * rsqrtf(fmaxf(var, 0.f) + BN_EPS);
            sa0 = a; sb0 = S.bS[tid] - m * a;
            m = S.statsD[tid] * invN;
            var = S.statsD[HD + tid] * invN - m * m;
            a = S.gD[tid] * rsqrtf(fmaxf(var, 0.f) + BN_EPS);
            sa1 = a; sb1 = S.bD[tid] - m * a;
        }
        affSa[tid] = sa0; affSb[tid] = sb0; affDa[tid] = sa1; affDb[tid] = sb1;
    } else {
        int r = tid - 128;
        int gr = row0 + r;
        degf[r] = (gr < N5) ? (float)(S.rowp[gr + 1] - S.rowp[gr]) : 0.f;
    }
    __syncthreads();

    // per-lane ldmatrix addressing constants
    int mi = lane >> 3;
    int lr = lane & 7;
    int a_kmi = mi >> 1;
    uint32_t a_off[2], a_xor[2];
#pragma unroll
    for (int mt = 0; mt < 2; mt++) {
        int r = warpM * 32 + mt * 16 + (mi & 1) * 8 + lr;
        a_off[mt] = r * 256;
        a_xor[mt] = r & 7;
    }
    int b_kmi = mi & 1;
    uint32_t b_off[4], b_xor[4];
#pragma unroll
    for (int jj = 0; jj < 4; jj++) {
        int r = warpN * 64 + jj * 16 + (mi >> 1) * 8 + lr;
        b_off[jj] = r * 256;
        b_xor[jj] = r & 7;
    }

    float acc[2][8][4];
#pragma unroll
    for (int mt = 0; mt < 2; mt++)
#pragma unroll
        for (int j = 0; j < 8; j++)
#pragma unroll
            for (int t = 0; t < 4; t++) acc[mt][j][t] = 0.f;

    for (int h = 0; h < 2; h++) {
        if (h) __syncthreads();               // prior MMAs consumed SMEM
        const float* As = h ? S.xprev : S.agg;
        const float* Bs = h ? S.wroot : S.wrel;
        const float* ka = h ? affDa : affSa;
        const float* kb = h ? affDb : affSb;
        // fill A tile: affine + bf16 hi/lo split, chunk-swizzled
#pragma unroll
        for (int i = 0; i < 8; i++) {
            int lin = tid + i * 256;
            int r = lin >> 4, c = lin & 15;
            int gr = row0 + r;
            float ds = h ? 1.f : degf[r];
            float4 v0 = make_float4(0.f,0.f,0.f,0.f), v1 = v0;
            if (gr < N5) {
                v0 = *(const float4*)(As + (size_t)gr * HD + c * 8);
                v1 = *(const float4*)(As + (size_t)gr * HD + c * 8 + 4);
            }
            float4 ka0 = *(const float4*)&ka[c * 8];
            float4 ka1 = *(const float4*)&ka[c * 8 + 4];
            float4 kb0 = *(const float4*)&kb[c * 8];
            float4 kb1 = *(const float4*)&kb[c * 8 + 4];
            v0.x = ka0.x * v0.x + ds * kb0.x;
            v0.y = ka0.y * v0.y + ds * kb0.y;
            v0.z = ka0.z * v0.z + ds * kb0.z;
            v0.w = ka0.w * v0.w + ds * kb0.w;
            v1.x = ka1.x * v1.x + ds * kb1.x;
            v1.y = ka1.y * v1.y + ds * kb1.y;
            v1.z = ka1.z * v1.z + ds * kb1.z;
            v1.w = ka1.w * v1.w + ds * kb1.w;
            uint32_t h0,l0,h1,l1,h2,l2,h3,l3;
            split2(v0.x, v0.y, h0, l0); split2(v0.z, v0.w, h1, l1);
            split2(v1.x, v1.y, h2, l2); split2(v1.z, v1.w, h3, l3);
            int off = r * 256 + ((c ^ (r & 7)) << 4);
            *(uint4*)(smem + A_HI + off) = make_uint4(h0, h1, h2, h3);
            *(uint4*)(smem + A_LO + off) = make_uint4(l0, l1, l2, l3);
        }
        // fill B tile (weights, raw)
#pragma unroll
        for (int i = 0; i < 8; i++) {
            int lin = tid + i * 256;
            int r = lin >> 4, c = lin & 15;
            float4 v0 = *(const float4*)(Bs + (size_t)r * HD + c * 8);
            float4 v1 = *(const float4*)(Bs + (size_t)r * HD + c * 8 + 4);
            uint32_t h0,l0,h1,l1,h2,l2,h3,l3;
            split2(v0.x, v0.y, h0, l0); split2(v0.z, v0.w, h1, l1);
            split2(v1.x, v1.y, h2, l2); split2(v1.z, v1.w, h3, l3);
            int off = r * 256 + ((c ^ (r & 7)) << 4);
            *(uint4*)(smem + B_HI + off) = make_uint4(h0, h1, h2, h3);
            *(uint4*)(smem + B_LO + off) = make_uint4(l0, l1, l2, l3);
        }
        __syncthreads();

#pragma unroll
        for (int p = 0; p < 3; p++) {
            uint32_t bA = sb + ((p == 1) ? A_LO : A_HI);
            uint32_t bB = sb + ((p == 2) ? B_LO : B_HI);
#pragma unroll
            for (int ks = 0; ks < 8; ks++) {
                uint32_t afr[2][4];
#pragma unroll
                for (int mt = 0; mt < 2; mt++) {
                    uint32_t ck = (uint32_t)((ks << 1) | a_kmi) ^ a_xor[mt];
                    ldsm4(afr[mt], bA + a_off[mt] + (ck << 4));
                }
                uint32_t bfr[8][2];
#pragma unroll
                for (int jj = 0; jj < 4; jj++) {
                    uint32_t q[4];
                    uint32_t ck = (uint32_t)((ks << 1) | b_kmi) ^ b_xor[jj];
                    ldsm4(q, bB + b_off[jj] + (ck << 4));
                    bfr[2*jj][0] = q[0]; bfr[2*jj][1] = q[1];
                    bfr[2*jj+1][0] = q[2]; bfr[2*jj+1][1] = q[3];
                }
#pragma unroll
                for (int mt = 0; mt < 2; mt++)
#pragma unroll
                    for (int j = 0; j < 8; j++)
                        mma16816(acc[mt][j], afr[mt], bfr[j]);
            }
        }
    }
    __syncthreads();

    // stage accums into padded SMEM (conflict-free)
    float* smF = (float*)smem;
    float* ssum = (float*)(smem + SSUM_OFF);
    float* ssq  = (float*)(smem + SSQ_OFF);
    if (tid < 128) { ssum[tid] = 0.f; ssq[tid] = 0.f; }
#pragma unroll
    for (int mt = 0; mt < 2; mt++) {
        int r0 = warpM * 32 + mt * 16 + (lane >> 2);
        int c  = warpN * 64 + (lane & 3) * 2;
#pragma unroll
        for (int j = 0; j < 8; j++) {
            int cc = c + j * 8;
            *(float2*)&smF[r0 * SMF_STRIDE + cc]       = make_float2(acc[mt][j][0], acc[mt][j][1]);
            *(float2*)&smF[(r0 + 8) * SMF_STRIDE + cc] = make_float2(acc[mt][j][2], acc[mt][j][3]);
        }
    }
    __syncthreads();

    // bias + relu + coalesced store + BN stats
    {
        int c4 = tid & 31, rg = tid >> 5;
        float4 bv = *(const float4*)(S.bias + c4 * 4);
        float s0=0,s1=0,s2=0,s3=0,q0=0,q1=0,q2=0,q3=0;
#pragma unroll
        for (int it = 0; it < 16; it++) {
            int r = it * 8 + rg;
            int gr = row0 + r;
            if (gr < N5) {
                float4 v = *(float4*)&smF[r * SMF_STRIDE + c4 * 4];
                v.x = fmaxf(v.x + bv.x, 0.f);
                v.y = fmaxf(v.y + bv.y, 0.f);
                v.z = fmaxf(v.z + bv.z, 0.f);
                v.w = fmaxf(v.w + bv.w, 0.f);
                *(float4*)(S.out + (size_t)gr * HD + c4 * 4) = v;
                s0 += v.x; s1 += v.y; s2 += v.z; s3 += v.w;
                q0 += v.x*v.x; q1 += v.y*v.y; q2 += v.z*v.z; q3 += v.w*v.w;
            }
        }
        atomicAdd(&ssum[c4*4+0], s0); atomicAdd(&ssum[c4*4+1], s1);
        atomicAdd(&ssum[c4*4+2], s2); atomicAdd(&ssum[c4*4+3], s3);
        atomicAdd(&ssq[c4*4+0], q0);  atomicAdd(&ssq[c4*4+1], q1);
        atomicAdd(&ssq[c4*4+2], q2);  atomicAdd(&ssq[c4*4+3], q3);
    }
    __syncthreads();
    if (tid < 128) {
        atomicAdd(&S.statsAcc[tid], ssum[tid]);
        atomicAdd(&S.statsAcc[HD + tid], ssq[tid]);
    }
}

// ---------------- pooling with lazy BN (this-layer stats) -----------------------
__global__ void k_pool(const float* __restrict__ xu, const float* __restrict__ xi,
                       const int* __restrict__ su, const int* __restrict__ si,
                       const float* __restrict__ statsU, const float* __restrict__ gU,
                       const float* __restrict__ btU,
                       const float* __restrict__ statsI, const float* __restrict__ gI,
                       const float* __restrict__ btI,
                       float* __restrict__ feats) {
    int g = blockIdx.x, c = threadIdx.x;
    const float invN = 1.f / (float)N5;
    float mU = statsU[c] * invN;
    float vU = statsU[HD + c] * invN - mU * mU;
    float aU = gU[c] * rsqrtf(fmaxf(vU, 0.f) + BN_EPS);
    float bU = btU[c] - mU * aU;
    float mI = statsI[c] * invN;
    float vI = statsI[HD + c] * invN - mI * mI;
    float aI = gI[c] * rsqrtf(fmaxf(vI, 0.f) + BN_EPS);
    float bI = btI[c] - mI * aI;

    int u0 = su[g], u1 = su[g + 1];
    int i0 = si[g], i1 = si[g + 1];
    float sumU = 0.f, sumI = 0.f;
    for (int r = u0; r < u1; r++) sumU += xu[(size_t)r * HD + c];
    for (int r = i0; r < i1; r++) sumI += xi[(size_t)r * HD + c];
    float nu = (float)(u1 - u0), ni = (float)(i1 - i0);
    float cnt = fmaxf(nu + ni, 1.f);
    feats[(size_t)g * HD + c] = (aU * sumU + nu * bU + aI * sumI + ni * bI) / cnt;
}

// ---------------- per-layer classifier heads ------------------------------------
__global__ void k_logits(const float* __restrict__ feats, const float* __restrict__ fcW,
                         const float* __restrict__ fcb, float* __restrict__ logits) {
    int idx = blockIdx.x * blockDim.x + threadIdx.x;
    if (idx >= NL * NG * NC) return;
    int l = idx / (NG * NC);
    int g = (idx / NC) % NG;
    int c = idx % NC;
    const float* f = feats + ((size_t)l * NG + g) * HD;
    const float* w = fcW + ((size_t)l * NC + c) * HD;
    float sum = fcb[l * NC + c];
#pragma unroll
    for (int k = 0; k < HD; k += 4) {
        float4 a = *(const float4*)(f + k);
        float4 b = *(const float4*)(w + k);
        sum += a.x * b.x + a.y * b.y + a.z * b.z + a.w * b.w;
    }
    logits[idx] = sum;
}

// ---------------- host orchestration -------------------------------------------
extern "C" void kernel_launch(void* const* d_in, const int* in_sizes, int n_in,
                              void* d_out, int out_size) {
    const float* x_user    = (const float*)d_in[0];
    const float* x_item    = (const float*)d_in[1];
    const int*   e_u2i     = (const int*)d_in[2];
    const int*   e_i2u     = (const int*)d_in[3];
    const int*   b_user    = (const int*)d_in[4];
    const int*   b_item    = (const int*)d_in[5];
    const float* Wrel_u2i  = (const float*)d_in[6];
    const float* Wroot_u2i = (const float*)d_in[7];
    const float* b_u2i     = (const float*)d_in[8];
    const float* Wrel_i2u  = (const float*)d_in[9];
    const float* Wroot_i2u = (const float*)d_in[10];
    const float* b_i2u     = (const float*)d_in[11];
    const float* bn_g_user = (const float*)d_in[12];
    const float* bn_b_user = (const float*)d_in[13];
    const float* bn_g_item = (const float*)d_in[14];
    const float* bn_b_item = (const float*)d_in[15];
    const float* fc_W      = (const float*)d_in[16];
    const float* fc_b      = (const float*)d_in[17];

    float* out   = (float*)d_out;
    float* feats = out + NL * NG * NC;

    float *xu, *xi, *newu, *newi, *aggu, *aggi, *stats;
    int *rowi, *rowu, *col_u2i, *col_i2u, *deg, *cur, *su, *si;
    cudaGetSymbolAddress((void**)&xu, g_xu);
    cudaGetSymbolAddress((void**)&xi, g_xi);
    cudaGetSymbolAddress((void**)&newu, g_newu);
    cudaGetSymbolAddress((void**)&newi, g_newi);
    cudaGetSymbolAddress((void**)&aggu, g_aggu);
    cudaGetSymbolAddress((void**)&aggi, g_aggi);
    cudaGetSymbolAddress((void**)&stats, g_stats);
    cudaGetSymbolAddress((void**)&rowi, g_rowi);
    cudaGetSymbolAddress((void**)&rowu, g_rowu);
    cudaGetSymbolAddress((void**)&col_u2i, g_col_u2i);
    cudaGetSymbolAddress((void**)&col_i2u, g_col_i2u);
    cudaGetSymbolAddress((void**)&deg, g_deg);
    cudaGetSymbolAddress((void**)&cur, g_cur);
    cudaGetSymbolAddress((void**)&su, g_su);
    cudaGetSymbolAddress((void**)&si, g_si);

    cudaFuncSetAttribute(k_gemm2, cudaFuncAttributeMaxDynamicSharedMemorySize, GEMM_SMEM);

    const int T = 256;
    const int NBLK = CDIV(N5, 128);   // 391 per side

    k_zero_f<<<CDIV(NL*2*2*HD, T), T>>>(stats, NL*2*2*HD);
    k_offsets<<<CDIV(NG+1, 128), 128>>>(b_user, NU, su);
    k_offsets<<<CDIV(NG+1, 128), 128>>>(b_item, NI, si);

    // CSR for u2i (dst = items)
    k_zero_i<<<CDIV(NI, T), T>>>(deg, NI);
    k_hist<<<CDIV(NE, T), T>>>(e_u2i + NE, deg);
    k_scan<<<1, 1024>>>(deg, NI, rowi);
    k_zero_i<<<CDIV(NI, T), T>>>(cur, NI);
    k_scatter<<<CDIV(NE, T), T>>>(e_u2i, e_u2i + NE, rowi, cur, col_u2i);

    // CSR for i2u (dst = users)
    k_zero_i<<<CDIV(NU, T), T>>>(deg, NU);
    k_hist<<<CDIV(NE, T), T>>>(e_i2u + NE, deg);
    k_scan<<<1, 1024>>>(deg, NU, rowu);
    k_zero_i<<<CDIV(NU, T), T>>>(cur, NU);
    k_scatter<<<CDIV(NE, T), T>>>(e_i2u, e_i2u + NE, rowu, cur, col_i2u);

    // raw-relu ping-pong: prev(l0)=inputs, cur(l0)=xu/xi; cur(l1)=newu/newi; cur(l2)=xu/xi
    const float* prevU = x_user;
    const float* prevI = x_item;
    float* bufsU[NL] = { xu, newu, xu };
    float* bufsI[NL] = { xi, newi, xi };

    for (int l = 0; l < NL; l++) {
        float* curU = bufsU[l];
        float* curI = bufsI[l];
        float* stats_u = stats + (size_t)(l*2 + 0) * 2 * HD;
        float* stats_i = stats + (size_t)(l*2 + 1) * 2 * HD;
        const float* pstats_u = (l > 0) ? stats + (size_t)((l-1)*2 + 0) * 2 * HD : stats;
        const float* pstats_i = (l > 0) ? stats + (size_t)((l-1)*2 + 1) * 2 * HD : stats;

        // aggregate raw features of both types in one launch
        k_agg2<<<CDIV((NI+NU)*32, T), T>>>(rowi, col_u2i, prevU, aggi,
                                           rowu, col_i2u, prevI, aggu);

        GemmSide SI; // computes new item features
        SI.agg = aggi; SI.xprev = prevI;
        SI.wrel = Wrel_u2i + (size_t)l*HD*HD; SI.wroot = Wroot_u2i + (size_t)l*HD*HD;
        SI.bias = b_u2i + (size_t)l*HD;
        SI.out = curI; SI.statsAcc = stats_i; SI.rowp = rowi;
        SI.statsS = pstats_u; SI.gS = bn_g_user; SI.bS = bn_b_user;   // source = users
        SI.statsD = pstats_i; SI.gD = bn_g_item; SI.bD = bn_b_item;   // dest   = items

        GemmSide SU; // computes new user features
        SU.agg = aggu; SU.xprev = prevU;
        SU.wrel = Wrel_i2u + (size_t)l*HD*HD; SU.wroot = Wroot_i2u + (size_t)l*HD*HD;
        SU.bias = b_i2u + (size_t)l*HD;
        SU.out = curU; SU.statsAcc = stats_u; SU.rowp = rowu;
        SU.statsS = pstats_i; SU.gS = bn_g_item; SU.bS = bn_b_item;   // source = items
        SU.statsD = pstats_u; SU.gD = bn_g_user; SU.bD = bn_b_user;   // dest   = users

        k_gemm2<<<2*NBLK, 256, GEMM_SMEM>>>(SI, SU, NBLK, l > 0 ? 1 : 0);

        k_pool<<<NG, HD>>>(curU, curI, su, si,
                           stats_u, bn_g_user, bn_b_user,
                           stats_i, bn_g_item, bn_b_item,
                           feats + (size_t)l*NG*HD);

        prevU = curU;
        prevI = curI;
    }

    k_logits<<<CDIV(NL*NG*NC, T), T>>>(feats, fc_W, fc_b, out);
}